// round 16
// baseline (speedup 1.0000x reference)
#include <cuda_runtime.h>
#include <math.h>
#include <stdint.h>

#define B_    32
#define NPTS  2048
#define S1_   512
#define K1_   48
#define S2_   128
#define K2_   64
#define F2RAW 4194304

typedef unsigned long long ull;

__device__ __forceinline__ ull fma2(ull a, ull b, ull c) {
    ull d; asm("fma.rn.f32x2 %0, %1, %2, %3;" : "=l"(d) : "l"(a), "l"(b), "l"(c)); return d;
}
__device__ __forceinline__ float lo32(ull v) { return __uint_as_float((unsigned)(v & 0xffffffffu)); }
__device__ __forceinline__ float hi32(ull v) { return __uint_as_float((unsigned)(v >> 32)); }
__device__ __forceinline__ ull dup32(float f) { unsigned u = __float_as_uint(f); return ((ull)u << 32) | (ull)u; }

// ---------------- scratch ----------------
__device__ float  g_xyz [B_*NPTS*3];
__device__ float  g_xyz1[B_*S1_*3];
__device__ float  g_xyz2[B_*S2_*3];
__device__ int    g_fi1 [B_*S1_];
__device__ int    g_fi2 [B_*S2_];
__device__ int    g_ni1 [B_*S1_*K1_];
__device__ int    g_ni2 [B_*S2_*K2_];
__device__ float  g_ya  [33554432];    // y2a (262144x128)
__device__ float  g_yb  [8388608];     // f1raw@0 (2M), f2raw@F2RAW (2M)
__device__ float  g_y3  [B_*S2_*512];
__device__ double g_psum[4194304];
__device__ double g_pssq[4194304];
__device__ float  g_scale[5*512];
__device__ float  g_bias [5*512];
// w1bT@0 (8192), w2aT pad 144x128 @8192, w2bT 128x512 @26624, w3T pad 528x512 @92160
__device__ float  g_wT  [393216];

// ---------------- fused prep ----------------
__global__ void k_prep(const float* __restrict__ pc, const float* __restrict__ w1b,
                       const float* __restrict__ w2a, const float* __restrict__ w2b,
                       const float* __restrict__ w3) {
    int idx = blockIdx.x * blockDim.x + threadIdx.x;
    if (idx < 65536) {
        int b = idx / NPTS, i = idx % NPTS;
        const float* p = pc + (size_t)b*3*NPTS + i;
        float x = p[0], y = p[NPTS], z = p[2*NPTS];
        float* o = g_xyz + (size_t)idx*3;
        o[0] = x; o[1] = y; o[2] = z;
    } else if (idx < 73728) {
        int i = idx - 65536;
        int o = i / 64, ic = i % 64;
        g_wT[ic*128 + o] = w1b[i];
    } else if (idx < 92160) {
        int i = idx - 73728;
        int r = i >> 7, oc = i & 127;
        g_wT[8192 + i] = (r < 134) ? w2a[oc*134 + r] : 0.f;
    } else if (idx < 157696) {
        int i = idx - 92160;
        int o = i / 128, ic = i % 128;
        g_wT[26624 + ic*512 + o] = w2b[i];
    } else if (idx < 428032) {
        int i = idx - 157696;
        int r = i >> 9, oc = i & 511;
        g_wT[92160 + i] = (r < 515) ? w3[oc*515 + r] : 0.f;
    }
}

// ---------------- FPS (exact) ----------------
template<int NPT>
__global__ void k_fps(const float* __restrict__ xyz, int n, int npoint,
                      int* __restrict__ fidx, float* __restrict__ oxyz) {
    const int b = blockIdx.x, tid = threadIdx.x;
    const float* base = xyz + (size_t)b*n*3;
    float lx[NPT], ly[NPT], lz[NPT], ld[NPT];
#pragma unroll
    for (int j = 0; j < NPT; j++) {
        int i = tid + j*256;
        lx[j] = base[i*3]; ly[j] = base[i*3+1]; lz[j] = base[i*3+2];
        ld[j] = 1e10f;
    }
    __shared__ float spx, spy, spz;
    __shared__ float swv[8];
    __shared__ int   swi[8];
    if (tid == 0) { fidx[(size_t)b*npoint] = 0; spx = base[0]; spy = base[1]; spz = base[2]; }
    __syncthreads();
    for (int s = 1; s < npoint; s++) {
        float px = spx, py = spy, pz = spz;
        float bv = -1.0f; int bi = 0;
#pragma unroll
        for (int j = 0; j < NPT; j++) {
            float dx = lx[j]-px, dy = ly[j]-py, dz = lz[j]-pz;
            float d = __fadd_rn(__fadd_rn(__fmul_rn(dx,dx), __fmul_rn(dy,dy)), __fmul_rn(dz,dz));
            float nd = fminf(ld[j], d); ld[j] = nd;
            int i = tid + j*256;
            if (nd > bv) { bv = nd; bi = i; }
        }
#pragma unroll
        for (int off = 16; off; off >>= 1) {
            float ov = __shfl_down_sync(0xffffffffu, bv, off);
            int   oi = __shfl_down_sync(0xffffffffu, bi, off);
            if (ov > bv || (ov == bv && oi < bi)) { bv = ov; bi = oi; }
        }
        if ((tid & 31) == 0) { swv[tid>>5] = bv; swi[tid>>5] = bi; }
        __syncthreads();
        if (tid == 0) {
            float v = swv[0]; int ii = swi[0];
#pragma unroll
            for (int w = 1; w < 8; w++)
                if (swv[w] > v || (swv[w] == v && swi[w] < ii)) { v = swv[w]; ii = swi[w]; }
            fidx[(size_t)b*npoint + s] = ii;
            spx = base[ii*3]; spy = base[ii*3+1]; spz = base[ii*3+2];
        }
        __syncthreads();
    }
    for (int s = tid; s < npoint; s += 256) {
        int ii = fidx[(size_t)b*npoint + s];
        oxyz[((size_t)b*npoint + s)*3 + 0] = base[ii*3];
        oxyz[((size_t)b*npoint + s)*3 + 1] = base[ii*3+1];
        oxyz[((size_t)b*npoint + s)*3 + 2] = base[ii*3+2];
    }
}

// ---------------- ball query (exact) ----------------
__global__ void k_ballquery(const float* __restrict__ xyz, const float* __restrict__ ctr,
                            int* __restrict__ ni, int n, int S, int ns, float r2, int nwarps) {
    int gw = (blockIdx.x * blockDim.x + threadIdx.x) >> 5;
    int lane = threadIdx.x & 31;
    if (gw >= nwarps) return;
    int b = gw / S, c = gw % S;
    const float* cp = ctr + ((size_t)b*S + c)*3;
    float cx = cp[0], cy = cp[1], cz = cp[2];
    const float* pb = xyz + (size_t)b*n*3;
    int* out = ni + (size_t)gw*ns;
    int cnt = 0, first = 0; bool havefirst = false;
    for (int base = 0; base < n; base += 32) {
        int i = base + lane;
        bool inr = false;
        if (i < n) {
            float dx = cx - pb[i*3], dy = cy - pb[i*3+1], dz = cz - pb[i*3+2];
            float d2 = __fadd_rn(__fadd_rn(__fmul_rn(dx,dx), __fmul_rn(dy,dy)), __fmul_rn(dz,dz));
            inr = d2 < r2;
        }
        unsigned m = __ballot_sync(0xffffffffu, inr);
        if (!havefirst && m) { first = base + __ffs(m) - 1; havefirst = true; }
        int pos = cnt + __popc(m & ((1u << lane) - 1u));
        if (inr && pos < ns) out[pos] = i;
        cnt += __popc(m);
        if (cnt >= ns) break;
    }
    if (cnt > ns) cnt = ns;
    if (!havefirst) first = 0;
    for (int j = cnt + lane; j < ns; j += 32) out[j] = first;
}

// ---------------- stage1a stats: 6x6 second moment + mean (float accumulators) ------
__global__ void k_stats6() {
    int tid = threadIdx.x;
    float M[21], mu[6];
#pragma unroll
    for (int e = 0; e < 21; e++) M[e] = 0.f;
#pragma unroll
    for (int i = 0; i < 6; i++) mu[i] = 0.f;
    int base = blockIdx.x * 1024;
    for (int it = 0; it < 4; it++) {
        int p = base + it*256 + tid;
        int bs = p / K1_;
        int b = bs >> 9;
        int nb = g_ni1[p];
        const float* gp = g_xyz  + ((size_t)b*NPTS + nb)*3;
        const float* cp = g_xyz1 + (size_t)bs*3;
        float h[6];
        h[0] = gp[0]-cp[0]; h[1] = gp[1]-cp[1]; h[2] = gp[2]-cp[2];
        h[3] = gp[0]; h[4] = gp[1]; h[5] = gp[2];
        int e = 0;
#pragma unroll
        for (int i = 0; i < 6; i++) {
            mu[i] += h[i];
#pragma unroll
            for (int j = i; j < 6; j++, e++) M[e] = fmaf(h[i], h[j], M[e]);
        }
    }
#pragma unroll
    for (int e = 0; e < 21; e++)
#pragma unroll
        for (int off = 16; off; off >>= 1) M[e] += __shfl_down_sync(0xffffffffu, M[e], off);
#pragma unroll
    for (int i = 0; i < 6; i++)
#pragma unroll
        for (int off = 16; off; off >>= 1) mu[i] += __shfl_down_sync(0xffffffffu, mu[i], off);
    __shared__ float sws[8][27];
    int lane = tid & 31, wid = tid >> 5;
    if (lane == 0) {
#pragma unroll
        for (int e = 0; e < 21; e++) sws[wid][e] = M[e];
#pragma unroll
        for (int i = 0; i < 6; i++) sws[wid][21+i] = mu[i];
    }
    __syncthreads();
    if (tid < 27) {
        double s = 0;
#pragma unroll
        for (int w = 0; w < 8; w++) s += (double)sws[w][tid];
        g_psum[blockIdx.x*32 + tid] = s;
    }
}

__global__ void k_quad6(const float* __restrict__ w1a, const float* __restrict__ gamma,
                        const float* __restrict__ beta) {
    __shared__ double sm[27];
    int tid = threadIdx.x;
    if (tid < 27) {
        double s = 0;
        for (int g = 0; g < 768; g++) s += g_psum[g*32 + tid];
        sm[tid] = s;
    }
    __syncthreads();
    if (tid < 64) {
        double w[6];
#pragma unroll
        for (int i = 0; i < 6; i++) w[i] = (double)w1a[tid*6 + i];
        double q = 0; int e = 0;
#pragma unroll
        for (int i = 0; i < 6; i++)
#pragma unroll
            for (int j = i; j < 6; j++, e++)
                q += (i == j ? 1.0 : 2.0) * w[i] * w[j] * sm[e];
        double mean = 0;
#pragma unroll
        for (int i = 0; i < 6; i++) mean += w[i] * sm[21+i];
        double cnt = 786432.0;
        mean /= cnt;
        double var = q/cnt - mean*mean;
        double a = (double)gamma[tid] / sqrt(var + 1e-5);
        g_scale[tid] = (float)a;
        g_bias[tid]  = (float)((double)beta[tid] - mean*a);
    }
}

// ---- fused stage1b: recompute y1a -> h1, GEMM 64->128, raw-max pool + stats --------
// thread tile: 4 w-pairs (8 oc) x 3 pts; ocq = tid>>4 (16), ptq = tid&15 (16x3=48)
__global__ void __launch_bounds__(256) k_fused1b(const float* __restrict__ w1a) {
    __shared__ float  sw[64*128];    // 32KB
    __shared__ ull    shd[64*49];    // 25KB h1 dupped, pitch 49
    __shared__ float  smaxf[2048];   // 8KB
    __shared__ double sredd[2048];   // 16KB
    __shared__ int    sni[48];
    __shared__ float  sxyz[144];
    __shared__ float  scent[3];
    int tid = threadIdx.x, bs = blockIdx.x, b = bs >> 9;
    if (tid < 48) sni[tid] = g_ni1[bs*48 + tid];
    if (tid >= 48 && tid < 51) scent[tid-48] = g_xyz1[(size_t)bs*3 + tid - 48];
    for (int i = tid; i < 2048; i += 256) ((float4*)sw)[i] = ((const float4*)g_wT)[i];
    __syncthreads();
    if (tid < 144) {
        int kk = tid / 3, d = tid - kk*3;
        sxyz[tid] = g_xyz[((size_t)b*NPTS + sni[kk])*3 + d];
    }
    __syncthreads();
    {
        int oc = tid & 63, kq = tid >> 6;
        float w0 = w1a[oc*6], w1 = w1a[oc*6+1], w2 = w1a[oc*6+2];
        float w3 = w1a[oc*6+3], w4 = w1a[oc*6+4], w5 = w1a[oc*6+5];
        float sc = g_scale[oc], bi = g_bias[oc];
#pragma unroll
        for (int i = 0; i < 12; i++) {
            int k = kq*12 + i;
            float gx = sxyz[k*3], gy = sxyz[k*3+1], gz = sxyz[k*3+2];
            float rx = gx - scent[0], ry = gy - scent[1], rz = gz - scent[2];
            float v = rx*w0 + ry*w1 + rz*w2 + gx*w3 + gy*w4 + gz*w5;
            shd[oc*49 + k] = dup32(fmaxf(fmaf(v, sc, bi), 0.f));
        }
    }
    __syncthreads();
    int ocq = tid >> 4, ptq = tid & 15;
    ull acc[4][3];
#pragma unroll
    for (int a = 0; a < 4; a++)
#pragma unroll
        for (int p = 0; p < 3; p++) acc[a][p] = 0ull;
#pragma unroll 4
    for (int j = 0; j < 64; j++) {
        ulonglong2 wA = *(const ulonglong2*)&sw[j*128 + ocq*8];
        ulonglong2 wB = *(const ulonglong2*)&sw[j*128 + ocq*8 + 4];
        const ull* hp = &shd[j*49 + ptq*3];
        ull h0 = hp[0], h1 = hp[1], h2 = hp[2];
        acc[0][0] = fma2(h0, wA.x, acc[0][0]); acc[0][1] = fma2(h1, wA.x, acc[0][1]); acc[0][2] = fma2(h2, wA.x, acc[0][2]);
        acc[1][0] = fma2(h0, wA.y, acc[1][0]); acc[1][1] = fma2(h1, wA.y, acc[1][1]); acc[1][2] = fma2(h2, wA.y, acc[1][2]);
        acc[2][0] = fma2(h0, wB.x, acc[2][0]); acc[2][1] = fma2(h1, wB.x, acc[2][1]); acc[2][2] = fma2(h2, wB.x, acc[2][2]);
        acc[3][0] = fma2(h0, wB.y, acc[3][0]); acc[3][1] = fma2(h1, wB.y, acc[3][1]); acc[3][2] = fma2(h2, wB.y, acc[3][2]);
    }
    // per-thread pool + stats over 3 pts
    float mlo[4], mhi[4]; double slo[4], shi[4], qlo[4], qhi[4];
#pragma unroll
    for (int a = 0; a < 4; a++) {
        float l0 = lo32(acc[a][0]), l1 = lo32(acc[a][1]), l2 = lo32(acc[a][2]);
        float u0 = hi32(acc[a][0]), u1 = hi32(acc[a][1]), u2 = hi32(acc[a][2]);
        mlo[a] = fmaxf(fmaxf(l0, l1), l2);
        mhi[a] = fmaxf(fmaxf(u0, u1), u2);
        slo[a] = (double)l0 + l1 + l2;  shi[a] = (double)u0 + u1 + u2;
        qlo[a] = (double)l0*l0 + (double)l1*l1 + (double)l2*l2;
        qhi[a] = (double)u0*u0 + (double)u1*u1 + (double)u2*u2;
    }
    __syncthreads();
#pragma unroll
    for (int a = 0; a < 4; a++) {
        smaxf[ptq*128 + ocq*8 + 2*a]     = mlo[a];
        smaxf[ptq*128 + ocq*8 + 2*a + 1] = mhi[a];
        sredd[ptq*128 + ocq*8 + 2*a]     = slo[a];
        sredd[ptq*128 + ocq*8 + 2*a + 1] = shi[a];
    }
    __syncthreads();
    if (tid < 128) {
        float m = smaxf[tid];
        double s = sredd[tid];
#pragma unroll
        for (int g = 1; g < 16; g++) { m = fmaxf(m, smaxf[g*128 + tid]); s += sredd[g*128 + tid]; }
        g_yb[(size_t)bs*128 + tid] = m;
        g_psum[(size_t)bs*128 + tid] = s;
    }
    __syncthreads();
#pragma unroll
    for (int a = 0; a < 4; a++) {
        sredd[ptq*128 + ocq*8 + 2*a]     = qlo[a];
        sredd[ptq*128 + ocq*8 + 2*a + 1] = qhi[a];
    }
    __syncthreads();
    if (tid < 128) {
        double s = sredd[tid];
#pragma unroll
        for (int g = 1; g < 16; g++) s += sredd[g*128 + tid];
        g_pssq[(size_t)bs*128 + tid] = s;
    }
}

// ---------------- finalize BN stats -> scale/bias ----------------
__global__ void k_finalize(const double* __restrict__ ps, const double* __restrict__ pq,
                           int G, int C, double cnt,
                           const float* __restrict__ gamma, const float* __restrict__ beta,
                           float* __restrict__ sc, float* __restrict__ bs_) {
    int c = blockIdx.x;
    double s = 0, q = 0;
    for (int g = threadIdx.x; g < G; g += 256) { s += ps[(size_t)g*C + c]; q += pq[(size_t)g*C + c]; }
    __shared__ double sd[256], sq_[256];
    sd[threadIdx.x] = s; sq_[threadIdx.x] = q;
    __syncthreads();
    for (int off = 128; off; off >>= 1) {
        if (threadIdx.x < off) { sd[threadIdx.x] += sd[threadIdx.x+off]; sq_[threadIdx.x] += sq_[threadIdx.x+off]; }
        __syncthreads();
    }
    if (threadIdx.x == 0) {
        double m = sd[0] / cnt;
        double v = sq_[0] / cnt - m*m;
        double inv = 1.0 / sqrt(v + 1e-5);
        double a = (double)gamma[c] * inv;
        sc[c]  = (float)a;
        bs_[c] = (float)((double)beta[c] - m*a);
    }
}

// ---------------- layer 2a: 134(pad144)->128, FFMA2, 32 pts/block ------------------
// f1 norm-relu fused into gather (f1raw in g_yb)
__global__ void __launch_bounds__(256) k_layer2a_t() {
    __shared__ float  sw[48*128];
    __shared__ float  shd[48*72];
    __shared__ double sred[1024];
    __shared__ int    sni[32];
    __shared__ float  scp[3];
    __shared__ float  sa1[128], sb1[128];
    int tid = threadIdx.x;
    int ocg = tid & 31, ptg = tid >> 5;
    int p0 = blockIdx.x * 32;
    int bs = p0 >> 6, b = bs >> 7;
    if (tid < 32) sni[tid] = g_ni2[p0 + tid];
    if (tid >= 32 && tid < 35) scp[tid-32] = g_xyz2[(size_t)bs*3 + tid - 32];
    if (tid >= 64 && tid < 192) { sa1[tid-64] = g_scale[512 + tid-64]; sb1[tid-64] = g_bias[512 + tid-64]; }
    ull accp[2][4];
#pragma unroll
    for (int pr = 0; pr < 2; pr++)
#pragma unroll
        for (int q = 0; q < 4; q++) accp[pr][q] = 0ull;
    for (int jc = 0; jc < 3; jc++) {
        __syncthreads();
        for (int i = tid; i < 1536; i += 256)
            ((float4*)sw)[i] = ((const float4*)(g_wT + 8192 + jc*48*128))[i];
        {
            int pt = tid >> 3, j0 = (tid & 7)*6;
            int nb = sni[pt];
            const float* f1p = g_yb  + ((size_t)b*S1_ + nb)*128;
            const float* gp  = g_xyz1 + ((size_t)b*S1_ + nb)*3;
#pragma unroll
            for (int k = 0; k < 6; k++) {
                int jj = j0 + k, ic = jc*48 + jj;
                float v;
                if (ic >= 134)     v = 0.f;
                else if (ic >= 6)  v = fmaxf(fmaf(f1p[ic-6], sa1[ic-6], sb1[ic-6]), 0.f);
                else if (ic >= 3)  v = gp[ic-3];
                else               v = gp[ic] - scp[ic];
                ((ull*)&shd[jj*72])[pt] = dup32(v);
            }
        }
        __syncthreads();
#pragma unroll 4
        for (int j = 0; j < 48; j++) {
            ulonglong2 wp = *(const ulonglong2*)&sw[j*128 + ocg*4];
            ulonglong2 h0 = *(const ulonglong2*)&shd[j*72 + ptg*8];
            ulonglong2 h1 = *(const ulonglong2*)&shd[j*72 + ptg*8 + 4];
            ull hh[4] = {h0.x, h0.y, h1.x, h1.y};
#pragma unroll
            for (int q = 0; q < 4; q++) {
                accp[0][q] = fma2(hh[q], wp.x, accp[0][q]);
                accp[1][q] = fma2(hh[q], wp.y, accp[1][q]);
            }
        }
    }
    double dsum[4] = {0,0,0,0}, dssq[4] = {0,0,0,0};
#pragma unroll
    for (int q = 0; q < 4; q++) {
        int pt = p0 + ptg*4 + q;
        float r0 = lo32(accp[0][q]), r1 = hi32(accp[0][q]);
        float r2 = lo32(accp[1][q]), r3 = hi32(accp[1][q]);
        float4 o; o.x = r0; o.y = r1; o.z = r2; o.w = r3;
        *(float4*)&g_ya[(size_t)pt*128 + ocg*4] = o;
        dsum[0] += r0; dssq[0] += (double)r0*r0;
        dsum[1] += r1; dssq[1] += (double)r1*r1;
        dsum[2] += r2; dssq[2] += (double)r2*r2;
        dsum[3] += r3; dssq[3] += (double)r3*r3;
    }
    __syncthreads();
#pragma unroll
    for (int a = 0; a < 4; a++) sred[ptg*128 + ocg*4 + a] = dsum[a];
    __syncthreads();
    if (tid < 128) {
        double s = 0;
#pragma unroll
        for (int g = 0; g < 8; g++) s += sred[g*128 + tid];
        g_psum[(size_t)blockIdx.x*128 + tid] = s;
    }
    __syncthreads();
#pragma unroll
    for (int a = 0; a < 4; a++) sred[ptg*128 + ocg*4 + a] = dssq[a];
    __syncthreads();
    if (tid < 128) {
        double s = 0;
#pragma unroll
        for (int g = 0; g < 8; g++) s += sred[g*128 + tid];
        g_pssq[(size_t)blockIdx.x*128 + tid] = s;
    }
}

// ---- fused stage2b: norm-relu(y2a) -> GEMM 128->512 (256-oc half) + raw-max + stats
__global__ void __launch_bounds__(256) k_fused2b() {
    __shared__ float  sw[16*256];    // 16KB
    __shared__ ull    shd[16*66];    // 8.45KB (64 pts dup, pitch 66)
    __shared__ float  smax[1024];    // 4KB
    __shared__ double sred[1024];    // 8KB
    int tid = threadIdx.x, bx = blockIdx.x;
    int cen = bx >> 1, half = bx & 1;
    int p0 = cen * 64, oco = half * 256;
    int ocq = tid & 63, ptg = tid >> 6;
    ull accp[2][16];
#pragma unroll
    for (int pr = 0; pr < 2; pr++)
#pragma unroll
        for (int q = 0; q < 16; q++) accp[pr][q] = 0ull;
    for (int jc = 0; jc < 8; jc++) {
        __syncthreads();
        for (int i = tid; i < 1024; i += 256) {
            int j = i >> 6, c4 = i & 63;
            ((float4*)sw)[i] = *(const float4*)&g_wT[26624 + (size_t)(jc*16 + j)*512 + oco + c4*4];
        }
        {
            int jj = tid & 15, ptb = tid >> 4;
            int ic = jc*16 + jj;
            float a = g_scale[1024 + ic], bb = g_bias[1024 + ic];
#pragma unroll
            for (int r = 0; r < 4; r++) {
                int pt = ptb + r*16;
                float v = g_ya[(size_t)(p0 + pt)*128 + ic];
                shd[jj*66 + pt] = dup32(fmaxf(fmaf(v, a, bb), 0.f));
            }
        }
        __syncthreads();
#pragma unroll
        for (int j = 0; j < 16; j++) {
            ulonglong2 wp = *(const ulonglong2*)&sw[j*256 + ocq*4];
#pragma unroll
            for (int q = 0; q < 8; q++) {
                ulonglong2 hh = *(const ulonglong2*)&shd[j*66 + ptg*16 + 2*q];
                accp[0][2*q]   = fma2(hh.x, wp.x, accp[0][2*q]);
                accp[0][2*q+1] = fma2(hh.y, wp.x, accp[0][2*q+1]);
                accp[1][2*q]   = fma2(hh.x, wp.y, accp[1][2*q]);
                accp[1][2*q+1] = fma2(hh.y, wp.y, accp[1][2*q+1]);
            }
        }
    }
    float mx[4] = {-1e30f, -1e30f, -1e30f, -1e30f};
    double ds[4] = {0,0,0,0}, dq[4] = {0,0,0,0};
#pragma unroll
    for (int pt = 0; pt < 16; pt++) {
        float y0 = lo32(accp[0][pt]), y1 = hi32(accp[0][pt]);
        float y2 = lo32(accp[1][pt]), y3 = hi32(accp[1][pt]);
        mx[0] = fmaxf(mx[0], y0); ds[0] += y0; dq[0] += (double)y0*y0;
        mx[1] = fmaxf(mx[1], y1); ds[1] += y1; dq[1] += (double)y1*y1;
        mx[2] = fmaxf(mx[2], y2); ds[2] += y2; dq[2] += (double)y2*y2;
        mx[3] = fmaxf(mx[3], y3); ds[3] += y3; dq[3] += (double)y3*y3;
    }
    __syncthreads();
#pragma unroll
    for (int a = 0; a < 4; a++) smax[ptg*256 + ocq*4 + a] = mx[a];
    __syncthreads();
    {
        float fm = fmaxf(fmaxf(smax[tid], smax[256 + tid]), fmaxf(smax[512 + tid], smax[768 + tid]));
        g_yb[F2RAW + (size_t)cen*512 + oco + tid] = fm;
    }
    __syncthreads();
#pragma unroll
    for (int a = 0; a < 4; a++) sred[ptg*256 + ocq*4 + a] = ds[a];
    __syncthreads();
    g_psum[(size_t)cen*512 + oco + tid] = sred[tid] + sred[256+tid] + sred[512+tid] + sred[768+tid];
    __syncthreads();
#pragma unroll
    for (int a = 0; a < 4; a++) sred[ptg*256 + ocq*4 + a] = dq[a];
    __syncthreads();
    g_pssq[(size_t)cen*512 + oco + tid] = sred[tid] + sred[256+tid] + sred[512+tid] + sred[768+tid];
}

// ---- layer 3: 515(pad528)->512, FFMA2, CTA=16pt x 512oc, f2 norm fused -------------
__global__ void __launch_bounds__(256) k_layer3_t() {
    __shared__ float  sw[16*512];
    __shared__ float  shd[16*32];
    __shared__ double sred[1024];
    __shared__ float  sa2[512], sb2[512];
    int tid = threadIdx.x;
    int ocg = tid & 127, ptg = tid >> 7;
    int p0 = blockIdx.x * 16;
    for (int i = tid; i < 512; i += 256) { sa2[i] = g_scale[1536 + i]; sb2[i] = g_bias[1536 + i]; }
    ull accp[2][8];
#pragma unroll
    for (int pr = 0; pr < 2; pr++)
#pragma unroll
        for (int q = 0; q < 8; q++) accp[pr][q] = 0ull;
    for (int jc = 0; jc < 33; jc++) {
        __syncthreads();
        for (int i = tid; i < 2048; i += 256)
            ((float4*)sw)[i] = ((const float4*)(g_wT + 92160 + jc*16*512))[i];
        {
            int pt = tid >> 4, jj = tid & 15;
            int ic = jc*16 + jj;
            float v;
            if (ic < 3)        v = g_xyz2[(size_t)(p0+pt)*3 + ic];
            else if (ic < 515) v = fmaxf(fmaf(g_yb[F2RAW + (size_t)(p0+pt)*512 + ic - 3],
                                              sa2[ic-3], sb2[ic-3]), 0.f);
            else               v = 0.f;
            ((ull*)&shd[jj*32])[pt] = dup32(v);
        }
        __syncthreads();
#pragma unroll
        for (int j = 0; j < 16; j++) {
            ulonglong2 wp = *(const ulonglong2*)&sw[j*512 + ocg*4];
            ulonglong2 h0 = *(const ulonglong2*)&shd[j*32 + ptg*16];
            ulonglong2 h1 = *(const ulonglong2*)&shd[j*32 + ptg*16 + 4];
            ulonglong2 h2 = *(const ulonglong2*)&shd[j*32 + ptg*16 + 8];
            ulonglong2 h3 = *(const ulonglong2*)&shd[j*32 + ptg*16 + 12];
            ull hh[8] = {h0.x, h0.y, h1.x, h1.y, h2.x, h2.y, h3.x, h3.y};
#pragma unroll
            for (int q = 0; q < 8; q++) {
                accp[0][q] = fma2(hh[q], wp.x, accp[0][q]);
                accp[1][q] = fma2(hh[q], wp.y, accp[1][q]);
            }
        }
    }
    double dsum[4] = {0,0,0,0}, dssq[4] = {0,0,0,0};
#pragma unroll
    for (int q = 0; q < 8; q++) {
        int pt = p0 + ptg*8 + q;
        float r0 = lo32(accp[0][q]), r1 = hi32(accp[0][q]);
        float r2 = lo32(accp[1][q]), r3 = hi32(accp[1][q]);
        float4 o; o.x = r0; o.y = r1; o.z = r2; o.w = r3;
        *(float4*)&g_y3[(size_t)pt*512 + ocg*4] = o;
        dsum[0] += r0; dssq[0] += (double)r0*r0;
        dsum[1] += r1; dssq[1] += (double)r1*r1;
        dsum[2] += r2; dssq[2] += (double)r2*r2;
        dsum[3] += r3; dssq[3] += (double)r3*r3;
    }
    __syncthreads();
#pragma unroll
    for (int a = 0; a < 4; a++) sred[ptg*512 + ocg*4 + a] = dsum[a];
    __syncthreads();
    for (int c = tid; c < 512; c += 256)
        g_psum[(size_t)blockIdx.x*512 + c] = sred[c] + sred[512 + c];
    __syncthreads();
#pragma unroll
    for (int a = 0; a < 4; a++) sred[ptg*512 + ocg*4 + a] = dssq[a];
    __syncthreads();
    for (int c = tid; c < 512; c += 256)
        g_pssq[(size_t)blockIdx.x*512 + c] = sred[c] + sred[512 + c];
}

// ---------------- final: norm-relu + max over 128 centroids ------------------------
__global__ void k_final(float* __restrict__ out) {
    int idx = blockIdx.x * blockDim.x + threadIdx.x;
    if (idx >= B_*512) return;
    int oc = idx & 511, b = idx >> 9;
    float a = g_scale[2048 + oc], bb = g_bias[2048 + oc];
    const float* base = g_y3 + (size_t)b*S2_*512 + oc;
    float m = 0.f;
#pragma unroll 8
    for (int p = 0; p < S2_; p++) {
        float v = fmaxf(fmaf(base[p*512], a, bb), 0.f);
        m = fmaxf(m, v);
    }
    out[idx] = m;
}

// ---------------- host ----------------
extern "C" void kernel_launch(void* const* d_in, const int* in_sizes, int n_in,
                              void* d_out, int out_size) {
    const float* pc  = (const float*)d_in[0];
    const float* w1a = (const float*)d_in[1];
    const float* g1a = (const float*)d_in[2];
    const float* b1a = (const float*)d_in[3];
    const float* w1b = (const float*)d_in[4];
    const float* g1b = (const float*)d_in[5];
    const float* b1b = (const float*)d_in[6];
    const float* w2a = (const float*)d_in[7];
    const float* g2a = (const float*)d_in[8];
    const float* b2a = (const float*)d_in[9];
    const float* w2b = (const float*)d_in[10];
    const float* g2b = (const float*)d_in[11];
    const float* b2b = (const float*)d_in[12];
    const float* w3  = (const float*)d_in[13];
    const float* g3  = (const float*)d_in[14];
    const float* b3  = (const float*)d_in[15];
    float* out = (float*)d_out;

    float *xyz, *xyz1, *xyz2, *scale, *bias;
    int *fi1, *fi2, *ni1, *ni2;
    double *psum, *pssq;
    cudaGetSymbolAddress((void**)&xyz,   g_xyz);
    cudaGetSymbolAddress((void**)&xyz1,  g_xyz1);
    cudaGetSymbolAddress((void**)&xyz2,  g_xyz2);
    cudaGetSymbolAddress((void**)&fi1,   g_fi1);
    cudaGetSymbolAddress((void**)&fi2,   g_fi2);
    cudaGetSymbolAddress((void**)&ni1,   g_ni1);
    cudaGetSymbolAddress((void**)&ni2,   g_ni2);
    cudaGetSymbolAddress((void**)&psum,  g_psum);
    cudaGetSymbolAddress((void**)&pssq,  g_pssq);
    cudaGetSymbolAddress((void**)&scale, g_scale);
    cudaGetSymbolAddress((void**)&bias,  g_bias);

    k_prep<<<1672, 256>>>(pc, w1b, w2a, w2b, w3);

    // stage 1
    k_fps<8><<<32, 256>>>(xyz, 2048, 512, fi1, xyz1);
    k_ballquery<<<2048, 256>>>(xyz, xyz1, ni1, 2048, 512, 48,
                               (float)(0.23*0.23), 32*512);
    k_stats6<<<768, 256>>>();
    k_quad6<<<1, 256>>>(w1a, g1a, b1a);
    k_fused1b<<<16384, 256>>>(w1a);
    k_finalize<<<128, 256>>>(psum, pssq, 16384, 128, 786432.0,
                             g1b, b1b, scale + 512, bias + 512);

    // stage 2
    k_fps<2><<<32, 256>>>(xyz1, 512, 128, fi2, xyz2);
    k_ballquery<<<512, 256>>>(xyz1, xyz2, ni2, 512, 128, 64,
                              (float)(0.32*0.32), 32*128);
    k_layer2a_t<<<8192, 256>>>();
    k_finalize<<<128, 256>>>(psum, pssq, 8192, 128, 262144.0,
                             g2a, b2a, scale + 1024, bias + 1024);
    k_fused2b<<<8192, 256>>>();
    k_finalize<<<512, 256>>>(psum, pssq, 4096, 512, 262144.0,
                             g2b, b2b, scale + 1536, bias + 1536);

    // stage 3
    k_layer3_t<<<256, 256>>>();
    k_finalize<<<512, 256>>>(psum, pssq, 256, 512, 4096.0,
                             g3, b3, scale + 2048, bias + 2048);
    k_final<<<64, 256>>>(out);
}

// round 17
// speedup vs baseline: 1.0505x; 1.0505x over previous
#include <cuda_runtime.h>
#include <math.h>
#include <stdint.h>

#define B_    32
#define NPTS  2048
#define S1_   512
#define K1_   48
#define S2_   128
#define K2_   64
#define F2RAW 4194304

typedef unsigned long long ull;

__device__ __forceinline__ ull fma2(ull a, ull b, ull c) {
    ull d; asm("fma.rn.f32x2 %0, %1, %2, %3;" : "=l"(d) : "l"(a), "l"(b), "l"(c)); return d;
}
__device__ __forceinline__ float lo32(ull v) { return __uint_as_float((unsigned)(v & 0xffffffffu)); }
__device__ __forceinline__ float hi32(ull v) { return __uint_as_float((unsigned)(v >> 32)); }
__device__ __forceinline__ ull dup32(float f) { unsigned u = __float_as_uint(f); return ((ull)u << 32) | (ull)u; }

// ---------------- scratch ----------------
__device__ float  g_xyz [B_*NPTS*3];
__device__ float  g_xyz1[B_*S1_*3];
__device__ float  g_xyz2[B_*S2_*3];
__device__ int    g_fi1 [B_*S1_];
__device__ int    g_fi2 [B_*S2_];
__device__ int    g_ni1 [B_*S1_*K1_];
__device__ int    g_ni2 [B_*S2_*K2_];
__device__ float  g_ya  [33554432];    // y2a (262144x128)
__device__ float  g_yb  [8388608];     // f1raw@0 (2M), f2raw@F2RAW (2M)
__device__ float  g_y3  [B_*S2_*512];
__device__ double g_psum[4194304];
__device__ double g_pssq[4194304];
__device__ float  g_scale[5*512];
__device__ float  g_bias [5*512];
// w1bT@0 (8192), w2aT pad 144x128 @8192, w2bT 128x512 @26624, w3T pad 528x512 @92160
__device__ float  g_wT  [393216];

// ---------------- fused prep ----------------
__global__ void k_prep(const float* __restrict__ pc, const float* __restrict__ w1b,
                       const float* __restrict__ w2a, const float* __restrict__ w2b,
                       const float* __restrict__ w3) {
    int idx = blockIdx.x * blockDim.x + threadIdx.x;
    if (idx < 65536) {
        int b = idx / NPTS, i = idx % NPTS;
        const float* p = pc + (size_t)b*3*NPTS + i;
        float x = p[0], y = p[NPTS], z = p[2*NPTS];
        float* o = g_xyz + (size_t)idx*3;
        o[0] = x; o[1] = y; o[2] = z;
    } else if (idx < 73728) {
        int i = idx - 65536;
        int o = i / 64, ic = i % 64;
        g_wT[ic*128 + o] = w1b[i];
    } else if (idx < 92160) {
        int i = idx - 73728;
        int r = i >> 7, oc = i & 127;
        g_wT[8192 + i] = (r < 134) ? w2a[oc*134 + r] : 0.f;
    } else if (idx < 157696) {
        int i = idx - 92160;
        int o = i / 128, ic = i % 128;
        g_wT[26624 + ic*512 + o] = w2b[i];
    } else if (idx < 428032) {
        int i = idx - 157696;
        int r = i >> 9, oc = i & 511;
        g_wT[92160 + i] = (r < 515) ? w3[oc*515 + r] : 0.f;
    }
}

// ---------------- FPS (exact) ----------------
template<int NPT>
__global__ void k_fps(const float* __restrict__ xyz, int n, int npoint,
                      int* __restrict__ fidx, float* __restrict__ oxyz) {
    const int b = blockIdx.x, tid = threadIdx.x;
    const float* base = xyz + (size_t)b*n*3;
    float lx[NPT], ly[NPT], lz[NPT], ld[NPT];
#pragma unroll
    for (int j = 0; j < NPT; j++) {
        int i = tid + j*256;
        lx[j] = base[i*3]; ly[j] = base[i*3+1]; lz[j] = base[i*3+2];
        ld[j] = 1e10f;
    }
    __shared__ float spx, spy, spz;
    __shared__ float swv[8];
    __shared__ int   swi[8];
    if (tid == 0) { fidx[(size_t)b*npoint] = 0; spx = base[0]; spy = base[1]; spz = base[2]; }
    __syncthreads();
    for (int s = 1; s < npoint; s++) {
        float px = spx, py = spy, pz = spz;
        float bv = -1.0f; int bi = 0;
#pragma unroll
        for (int j = 0; j < NPT; j++) {
            float dx = lx[j]-px, dy = ly[j]-py, dz = lz[j]-pz;
            float d = __fadd_rn(__fadd_rn(__fmul_rn(dx,dx), __fmul_rn(dy,dy)), __fmul_rn(dz,dz));
            float nd = fminf(ld[j], d); ld[j] = nd;
            int i = tid + j*256;
            if (nd > bv) { bv = nd; bi = i; }
        }
#pragma unroll
        for (int off = 16; off; off >>= 1) {
            float ov = __shfl_down_sync(0xffffffffu, bv, off);
            int   oi = __shfl_down_sync(0xffffffffu, bi, off);
            if (ov > bv || (ov == bv && oi < bi)) { bv = ov; bi = oi; }
        }
        if ((tid & 31) == 0) { swv[tid>>5] = bv; swi[tid>>5] = bi; }
        __syncthreads();
        if (tid == 0) {
            float v = swv[0]; int ii = swi[0];
#pragma unroll
            for (int w = 1; w < 8; w++)
                if (swv[w] > v || (swv[w] == v && swi[w] < ii)) { v = swv[w]; ii = swi[w]; }
            fidx[(size_t)b*npoint + s] = ii;
            spx = base[ii*3]; spy = base[ii*3+1]; spz = base[ii*3+2];
        }
        __syncthreads();
    }
    for (int s = tid; s < npoint; s += 256) {
        int ii = fidx[(size_t)b*npoint + s];
        oxyz[((size_t)b*npoint + s)*3 + 0] = base[ii*3];
        oxyz[((size_t)b*npoint + s)*3 + 1] = base[ii*3+1];
        oxyz[((size_t)b*npoint + s)*3 + 2] = base[ii*3+2];
    }
}

// ---------------- ball query (exact) ----------------
__global__ void k_ballquery(const float* __restrict__ xyz, const float* __restrict__ ctr,
                            int* __restrict__ ni, int n, int S, int ns, float r2, int nwarps) {
    int gw = (blockIdx.x * blockDim.x + threadIdx.x) >> 5;
    int lane = threadIdx.x & 31;
    if (gw >= nwarps) return;
    int b = gw / S, c = gw % S;
    const float* cp = ctr + ((size_t)b*S + c)*3;
    float cx = cp[0], cy = cp[1], cz = cp[2];
    const float* pb = xyz + (size_t)b*n*3;
    int* out = ni + (size_t)gw*ns;
    int cnt = 0, first = 0; bool havefirst = false;
    for (int base = 0; base < n; base += 32) {
        int i = base + lane;
        bool inr = false;
        if (i < n) {
            float dx = cx - pb[i*3], dy = cy - pb[i*3+1], dz = cz - pb[i*3+2];
            float d2 = __fadd_rn(__fadd_rn(__fmul_rn(dx,dx), __fmul_rn(dy,dy)), __fmul_rn(dz,dz));
            inr = d2 < r2;
        }
        unsigned m = __ballot_sync(0xffffffffu, inr);
        if (!havefirst && m) { first = base + __ffs(m) - 1; havefirst = true; }
        int pos = cnt + __popc(m & ((1u << lane) - 1u));
        if (inr && pos < ns) out[pos] = i;
        cnt += __popc(m);
        if (cnt >= ns) break;
    }
    if (cnt > ns) cnt = ns;
    if (!havefirst) first = 0;
    for (int j = cnt + lane; j < ns; j += 32) out[j] = first;
}

// ---------------- stage1a stats: 6x6 second moment + mean (float accumulators) ------
__global__ void k_stats6() {
    int tid = threadIdx.x;
    float M[21], mu[6];
#pragma unroll
    for (int e = 0; e < 21; e++) M[e] = 0.f;
#pragma unroll
    for (int i = 0; i < 6; i++) mu[i] = 0.f;
    int base = blockIdx.x * 1024;
    for (int it = 0; it < 4; it++) {
        int p = base + it*256 + tid;
        int bs = p / K1_;
        int b = bs >> 9;
        int nb = g_ni1[p];
        const float* gp = g_xyz  + ((size_t)b*NPTS + nb)*3;
        const float* cp = g_xyz1 + (size_t)bs*3;
        float h[6];
        h[0] = gp[0]-cp[0]; h[1] = gp[1]-cp[1]; h[2] = gp[2]-cp[2];
        h[3] = gp[0]; h[4] = gp[1]; h[5] = gp[2];
        int e = 0;
#pragma unroll
        for (int i = 0; i < 6; i++) {
            mu[i] += h[i];
#pragma unroll
            for (int j = i; j < 6; j++, e++) M[e] = fmaf(h[i], h[j], M[e]);
        }
    }
#pragma unroll
    for (int e = 0; e < 21; e++)
#pragma unroll
        for (int off = 16; off; off >>= 1) M[e] += __shfl_down_sync(0xffffffffu, M[e], off);
#pragma unroll
    for (int i = 0; i < 6; i++)
#pragma unroll
        for (int off = 16; off; off >>= 1) mu[i] += __shfl_down_sync(0xffffffffu, mu[i], off);
    __shared__ float sws[8][27];
    int lane = tid & 31, wid = tid >> 5;
    if (lane == 0) {
#pragma unroll
        for (int e = 0; e < 21; e++) sws[wid][e] = M[e];
#pragma unroll
        for (int i = 0; i < 6; i++) sws[wid][21+i] = mu[i];
    }
    __syncthreads();
    if (tid < 27) {
        double s = 0;
#pragma unroll
        for (int w = 0; w < 8; w++) s += (double)sws[w][tid];
        g_psum[blockIdx.x*32 + tid] = s;
    }
}

__global__ void k_quad6(const float* __restrict__ w1a, const float* __restrict__ gamma,
                        const float* __restrict__ beta) {
    __shared__ double sm[27];
    int tid = threadIdx.x;
    if (tid < 27) {
        double s = 0;
        for (int g = 0; g < 768; g++) s += g_psum[g*32 + tid];
        sm[tid] = s;
    }
    __syncthreads();
    if (tid < 64) {
        double w[6];
#pragma unroll
        for (int i = 0; i < 6; i++) w[i] = (double)w1a[tid*6 + i];
        double q = 0; int e = 0;
#pragma unroll
        for (int i = 0; i < 6; i++)
#pragma unroll
            for (int j = i; j < 6; j++, e++)
                q += (i == j ? 1.0 : 2.0) * w[i] * w[j] * sm[e];
        double mean = 0;
#pragma unroll
        for (int i = 0; i < 6; i++) mean += w[i] * sm[21+i];
        double cnt = 786432.0;
        mean /= cnt;
        double var = q/cnt - mean*mean;
        double a = (double)gamma[tid] / sqrt(var + 1e-5);
        g_scale[tid] = (float)a;
        g_bias[tid]  = (float)((double)beta[tid] - mean*a);
    }
}

// ---- fused stage1b: recompute y1a -> h1, GEMM 64->128, raw-max pool + stats --------
// (R13 proven shape: thread = 2oc x 12pt, warp-shuffle pool/stats)
__global__ void __launch_bounds__(256) k_fused1b(const float* __restrict__ w1a) {
    __shared__ float sw[64*128];    // 32KB
    __shared__ ull   shd[64*50];    // 25.6KB h1 dupped, pitch 50
    __shared__ int   sni[48];
    __shared__ float sxyz[144];
    __shared__ float scent[3];
    int tid = threadIdx.x, bs = blockIdx.x, b = bs >> 9;
    if (tid < 48) sni[tid] = g_ni1[bs*48 + tid];
    if (tid >= 48 && tid < 51) scent[tid-48] = g_xyz1[(size_t)bs*3 + tid - 48];
    for (int i = tid; i < 2048; i += 256) ((float4*)sw)[i] = ((const float4*)g_wT)[i];
    __syncthreads();
    if (tid < 144) {
        int kk = tid / 3, d = tid - kk*3;
        sxyz[tid] = g_xyz[((size_t)b*NPTS + sni[kk])*3 + d];
    }
    __syncthreads();
    {
        int oc = tid & 63, kq = tid >> 6;
        float w0 = w1a[oc*6], w1 = w1a[oc*6+1], w2 = w1a[oc*6+2];
        float w3 = w1a[oc*6+3], w4 = w1a[oc*6+4], w5 = w1a[oc*6+5];
        float sc = g_scale[oc], bi = g_bias[oc];
#pragma unroll
        for (int i = 0; i < 12; i++) {
            int k = kq*12 + i;
            float gx = sxyz[k*3], gy = sxyz[k*3+1], gz = sxyz[k*3+2];
            float rx = gx - scent[0], ry = gy - scent[1], rz = gz - scent[2];
            float v = rx*w0 + ry*w1 + rz*w2 + gx*w3 + gy*w4 + gz*w5;
            shd[oc*50 + k] = dup32(fmaxf(fmaf(v, sc, bi), 0.f));
        }
    }
    __syncthreads();
    int ocp = tid >> 2, kg = tid & 3;
    ull acc[12];
#pragma unroll
    for (int q = 0; q < 12; q++) acc[q] = 0ull;
#pragma unroll 4
    for (int j = 0; j < 64; j++) {
        ull wp = *(const ull*)&sw[j*128 + ocp*2];
        const ulonglong2* hp = (const ulonglong2*)&shd[j*50 + kg*12];
        ulonglong2 h0 = hp[0], h1 = hp[1], h2 = hp[2];
        ulonglong2 h3 = hp[3], h4 = hp[4], h5 = hp[5];
        acc[0]  = fma2(h0.x, wp, acc[0]);  acc[1]  = fma2(h0.y, wp, acc[1]);
        acc[2]  = fma2(h1.x, wp, acc[2]);  acc[3]  = fma2(h1.y, wp, acc[3]);
        acc[4]  = fma2(h2.x, wp, acc[4]);  acc[5]  = fma2(h2.y, wp, acc[5]);
        acc[6]  = fma2(h3.x, wp, acc[6]);  acc[7]  = fma2(h3.y, wp, acc[7]);
        acc[8]  = fma2(h4.x, wp, acc[8]);  acc[9]  = fma2(h4.y, wp, acc[9]);
        acc[10] = fma2(h5.x, wp, acc[10]); acc[11] = fma2(h5.y, wp, acc[11]);
    }
    float m0 = -1e30f, m1 = -1e30f;
    double ds0 = 0, ds1 = 0, dq0 = 0, dq1 = 0;
#pragma unroll
    for (int q = 0; q < 12; q++) {
        float y0 = lo32(acc[q]), y1 = hi32(acc[q]);
        m0 = fmaxf(m0, y0); m1 = fmaxf(m1, y1);
        ds0 += y0; dq0 += (double)y0*y0;
        ds1 += y1; dq1 += (double)y1*y1;
    }
#pragma unroll
    for (int off = 1; off < 4; off <<= 1) {
        m0 = fmaxf(m0, __shfl_xor_sync(0xffffffffu, m0, off));
        m1 = fmaxf(m1, __shfl_xor_sync(0xffffffffu, m1, off));
        ds0 += __shfl_xor_sync(0xffffffffu, ds0, off);
        ds1 += __shfl_xor_sync(0xffffffffu, ds1, off);
        dq0 += __shfl_xor_sync(0xffffffffu, dq0, off);
        dq1 += __shfl_xor_sync(0xffffffffu, dq1, off);
    }
    if (kg == 0) {
        size_t o = (size_t)bs*128 + ocp*2;
        g_yb[o] = m0;  g_yb[o+1] = m1;
        g_psum[o] = ds0; g_psum[o+1] = ds1;
        g_pssq[o] = dq0; g_pssq[o+1] = dq1;
    }
}

// ---------------- finalize BN stats -> scale/bias ----------------
__global__ void k_finalize(const double* __restrict__ ps, const double* __restrict__ pq,
                           int G, int C, double cnt,
                           const float* __restrict__ gamma, const float* __restrict__ beta,
                           float* __restrict__ sc, float* __restrict__ bs_) {
    int c = blockIdx.x;
    double s = 0, q = 0;
    for (int g = threadIdx.x; g < G; g += 256) { s += ps[(size_t)g*C + c]; q += pq[(size_t)g*C + c]; }
    __shared__ double sd[256], sq_[256];
    sd[threadIdx.x] = s; sq_[threadIdx.x] = q;
    __syncthreads();
    for (int off = 128; off; off >>= 1) {
        if (threadIdx.x < off) { sd[threadIdx.x] += sd[threadIdx.x+off]; sq_[threadIdx.x] += sq_[threadIdx.x+off]; }
        __syncthreads();
    }
    if (threadIdx.x == 0) {
        double m = sd[0] / cnt;
        double v = sq_[0] / cnt - m*m;
        double inv = 1.0 / sqrt(v + 1e-5);
        double a = (double)gamma[c] * inv;
        sc[c]  = (float)a;
        bs_[c] = (float)((double)beta[c] - m*a);
    }
}

// ---------------- layer 2a: 134(pad144)->128, FFMA2, 32 pts/block ------------------
// f1 norm-relu fused into gather (f1raw in g_yb)
__global__ void __launch_bounds__(256) k_layer2a_t() {
    __shared__ float  sw[48*128];
    __shared__ float  shd[48*72];
    __shared__ double sred[1024];
    __shared__ int    sni[32];
    __shared__ float  scp[3];
    __shared__ float  sa1[128], sb1[128];
    int tid = threadIdx.x;
    int ocg = tid & 31, ptg = tid >> 5;
    int p0 = blockIdx.x * 32;
    int bs = p0 >> 6, b = bs >> 7;
    if (tid < 32) sni[tid] = g_ni2[p0 + tid];
    if (tid >= 32 && tid < 35) scp[tid-32] = g_xyz2[(size_t)bs*3 + tid - 32];
    if (tid >= 64 && tid < 192) { sa1[tid-64] = g_scale[512 + tid-64]; sb1[tid-64] = g_bias[512 + tid-64]; }
    ull accp[2][4];
#pragma unroll
    for (int pr = 0; pr < 2; pr++)
#pragma unroll
        for (int q = 0; q < 4; q++) accp[pr][q] = 0ull;
    for (int jc = 0; jc < 3; jc++) {
        __syncthreads();
        for (int i = tid; i < 1536; i += 256)
            ((float4*)sw)[i] = ((const float4*)(g_wT + 8192 + jc*48*128))[i];
        {
            int pt = tid >> 3, j0 = (tid & 7)*6;
            int nb = sni[pt];
            const float* f1p = g_yb  + ((size_t)b*S1_ + nb)*128;
            const float* gp  = g_xyz1 + ((size_t)b*S1_ + nb)*3;
#pragma unroll
            for (int k = 0; k < 6; k++) {
                int jj = j0 + k, ic = jc*48 + jj;
                float v;
                if (ic >= 134)     v = 0.f;
                else if (ic >= 6)  v = fmaxf(fmaf(f1p[ic-6], sa1[ic-6], sb1[ic-6]), 0.f);
                else if (ic >= 3)  v = gp[ic-3];
                else               v = gp[ic] - scp[ic];
                ((ull*)&shd[jj*72])[pt] = dup32(v);
            }
        }
        __syncthreads();
#pragma unroll 4
        for (int j = 0; j < 48; j++) {
            ulonglong2 wp = *(const ulonglong2*)&sw[j*128 + ocg*4];
            ulonglong2 h0 = *(const ulonglong2*)&shd[j*72 + ptg*8];
            ulonglong2 h1 = *(const ulonglong2*)&shd[j*72 + ptg*8 + 4];
            ull hh[4] = {h0.x, h0.y, h1.x, h1.y};
#pragma unroll
            for (int q = 0; q < 4; q++) {
                accp[0][q] = fma2(hh[q], wp.x, accp[0][q]);
                accp[1][q] = fma2(hh[q], wp.y, accp[1][q]);
            }
        }
    }
    double dsum[4] = {0,0,0,0}, dssq[4] = {0,0,0,0};
#pragma unroll
    for (int q = 0; q < 4; q++) {
        int pt = p0 + ptg*4 + q;
        float r0 = lo32(accp[0][q]), r1 = hi32(accp[0][q]);
        float r2 = lo32(accp[1][q]), r3 = hi32(accp[1][q]);
        float4 o; o.x = r0; o.y = r1; o.z = r2; o.w = r3;
        *(float4*)&g_ya[(size_t)pt*128 + ocg*4] = o;
        dsum[0] += r0; dssq[0] += (double)r0*r0;
        dsum[1] += r1; dssq[1] += (double)r1*r1;
        dsum[2] += r2; dssq[2] += (double)r2*r2;
        dsum[3] += r3; dssq[3] += (double)r3*r3;
    }
    __syncthreads();
#pragma unroll
    for (int a = 0; a < 4; a++) sred[ptg*128 + ocg*4 + a] = dsum[a];
    __syncthreads();
    if (tid < 128) {
        double s = 0;
#pragma unroll
        for (int g = 0; g < 8; g++) s += sred[g*128 + tid];
        g_psum[(size_t)blockIdx.x*128 + tid] = s;
    }
    __syncthreads();
#pragma unroll
    for (int a = 0; a < 4; a++) sred[ptg*128 + ocg*4 + a] = dssq[a];
    __syncthreads();
    if (tid < 128) {
        double s = 0;
#pragma unroll
        for (int g = 0; g < 8; g++) s += sred[g*128 + tid];
        g_pssq[(size_t)blockIdx.x*128 + tid] = s;
    }
}

// ---- fused stage2b: norm-relu(y2a) -> GEMM 128->512 (256-oc half) + raw-max + stats
__global__ void __launch_bounds__(256) k_fused2b() {
    __shared__ float  sw[16*256];    // 16KB
    __shared__ ull    shd[16*66];    // 8.45KB (64 pts dup, pitch 66)
    __shared__ float  smax[1024];    // 4KB
    __shared__ double sred[1024];    // 8KB
    int tid = threadIdx.x, bx = blockIdx.x;
    int cen = bx >> 1, half = bx & 1;
    int p0 = cen * 64, oco = half * 256;
    int ocq = tid & 63, ptg = tid >> 6;
    ull accp[2][16];
#pragma unroll
    for (int pr = 0; pr < 2; pr++)
#pragma unroll
        for (int q = 0; q < 16; q++) accp[pr][q] = 0ull;
    for (int jc = 0; jc < 8; jc++) {
        __syncthreads();
        for (int i = tid; i < 1024; i += 256) {
            int j = i >> 6, c4 = i & 63;
            ((float4*)sw)[i] = *(const float4*)&g_wT[26624 + (size_t)(jc*16 + j)*512 + oco + c4*4];
        }
        {
            int jj = tid & 15, ptb = tid >> 4;
            int ic = jc*16 + jj;
            float a = g_scale[1024 + ic], bb = g_bias[1024 + ic];
#pragma unroll
            for (int r = 0; r < 4; r++) {
                int pt = ptb + r*16;
                float v = g_ya[(size_t)(p0 + pt)*128 + ic];
                shd[jj*66 + pt] = dup32(fmaxf(fmaf(v, a, bb), 0.f));
            }
        }
        __syncthreads();
#pragma unroll
        for (int j = 0; j < 16; j++) {
            ulonglong2 wp = *(const ulonglong2*)&sw[j*256 + ocq*4];
#pragma unroll
            for (int q = 0; q < 8; q++) {
                ulonglong2 hh = *(const ulonglong2*)&shd[j*66 + ptg*16 + 2*q];
                accp[0][2*q]   = fma2(hh.x, wp.x, accp[0][2*q]);
                accp[0][2*q+1] = fma2(hh.y, wp.x, accp[0][2*q+1]);
                accp[1][2*q]   = fma2(hh.x, wp.y, accp[1][2*q]);
                accp[1][2*q+1] = fma2(hh.y, wp.y, accp[1][2*q+1]);
            }
        }
    }
    float mx[4] = {-1e30f, -1e30f, -1e30f, -1e30f};
    double ds[4] = {0,0,0,0}, dq[4] = {0,0,0,0};
#pragma unroll
    for (int pt = 0; pt < 16; pt++) {
        float y0 = lo32(accp[0][pt]), y1 = hi32(accp[0][pt]);
        float y2 = lo32(accp[1][pt]), y3 = hi32(accp[1][pt]);
        mx[0] = fmaxf(mx[0], y0); ds[0] += y0; dq[0] += (double)y0*y0;
        mx[1] = fmaxf(mx[1], y1); ds[1] += y1; dq[1] += (double)y1*y1;
        mx[2] = fmaxf(mx[2], y2); ds[2] += y2; dq[2] += (double)y2*y2;
        mx[3] = fmaxf(mx[3], y3); ds[3] += y3; dq[3] += (double)y3*y3;
    }
    __syncthreads();
#pragma unroll
    for (int a = 0; a < 4; a++) smax[ptg*256 + ocq*4 + a] = mx[a];
    __syncthreads();
    {
        float fm = fmaxf(fmaxf(smax[tid], smax[256 + tid]), fmaxf(smax[512 + tid], smax[768 + tid]));
        g_yb[F2RAW + (size_t)cen*512 + oco + tid] = fm;
    }
    __syncthreads();
#pragma unroll
    for (int a = 0; a < 4; a++) sred[ptg*256 + ocq*4 + a] = ds[a];
    __syncthreads();
    g_psum[(size_t)cen*512 + oco + tid] = sred[tid] + sred[256+tid] + sred[512+tid] + sred[768+tid];
    __syncthreads();
#pragma unroll
    for (int a = 0; a < 4; a++) sred[ptg*256 + ocq*4 + a] = dq[a];
    __syncthreads();
    g_pssq[(size_t)cen*512 + oco + tid] = sred[tid] + sred[256+tid] + sred[512+tid] + sred[768+tid];
}

// ---- layer 3: 515(pad528)->512, FFMA2, CTA=16pt x 512oc, f2 norm fused -------------
__global__ void __launch_bounds__(256) k_layer3_t() {
    __shared__ float  sw[16*512];
    __shared__ float  shd[16*32];
    __shared__ double sred[1024];
    __shared__ float  sa2[512], sb2[512];
    int tid = threadIdx.x;
    int ocg = tid & 127, ptg = tid >> 7;
    int p0 = blockIdx.x * 16;
    for (int i = tid; i < 512; i += 256) { sa2[i] = g_scale[1536 + i]; sb2[i] = g_bias[1536 + i]; }
    ull accp[2][8];
#pragma unroll
    for (int pr = 0; pr < 2; pr++)
#pragma unroll
        for (int q = 0; q < 8; q++) accp[pr][q] = 0ull;
    for (int jc = 0; jc < 33; jc++) {
        __syncthreads();
        for (int i = tid; i < 2048; i += 256)
            ((float4*)sw)[i] = ((const float4*)(g_wT + 92160 + jc*16*512))[i];
        {
            int pt = tid >> 4, jj = tid & 15;
            int ic = jc*16 + jj;
            float v;
            if (ic < 3)        v = g_xyz2[(size_t)(p0+pt)*3 + ic];
            else if (ic < 515) v = fmaxf(fmaf(g_yb[F2RAW + (size_t)(p0+pt)*512 + ic - 3],
                                              sa2[ic-3], sb2[ic-3]), 0.f);
            else               v = 0.f;
            ((ull*)&shd[jj*32])[pt] = dup32(v);
        }
        __syncthreads();
#pragma unroll
        for (int j = 0; j < 16; j++) {
            ulonglong2 wp = *(const ulonglong2*)&sw[j*512 + ocg*4];
            ulonglong2 h0 = *(const ulonglong2*)&shd[j*32 + ptg*16];
            ulonglong2 h1 = *(const ulonglong2*)&shd[j*32 + ptg*16 + 4];
            ulonglong2 h2 = *(const ulonglong2*)&shd[j*32 + ptg*16 + 8];
            ulonglong2 h3 = *(const ulonglong2*)&shd[j*32 + ptg*16 + 12];
            ull hh[8] = {h0.x, h0.y, h1.x, h1.y, h2.x, h2.y, h3.x, h3.y};
#pragma unroll
            for (int q = 0; q < 8; q++) {
                accp[0][q] = fma2(hh[q], wp.x, accp[0][q]);
                accp[1][q] = fma2(hh[q], wp.y, accp[1][q]);
            }
        }
    }
    double dsum[4] = {0,0,0,0}, dssq[4] = {0,0,0,0};
#pragma unroll
    for (int q = 0; q < 8; q++) {
        int pt = p0 + ptg*8 + q;
        float r0 = lo32(accp[0][q]), r1 = hi32(accp[0][q]);
        float r2 = lo32(accp[1][q]), r3 = hi32(accp[1][q]);
        float4 o; o.x = r0; o.y = r1; o.z = r2; o.w = r3;
        *(float4*)&g_y3[(size_t)pt*512 + ocg*4] = o;
        dsum[0] += r0; dssq[0] += (double)r0*r0;
        dsum[1] += r1; dssq[1] += (double)r1*r1;
        dsum[2] += r2; dssq[2] += (double)r2*r2;
        dsum[3] += r3; dssq[3] += (double)r3*r3;
    }
    __syncthreads();
#pragma unroll
    for (int a = 0; a < 4; a++) sred[ptg*512 + ocg*4 + a] = dsum[a];
    __syncthreads();
    for (int c = tid; c < 512; c += 256)
        g_psum[(size_t)blockIdx.x*512 + c] = sred[c] + sred[512 + c];
    __syncthreads();
#pragma unroll
    for (int a = 0; a < 4; a++) sred[ptg*512 + ocg*4 + a] = dssq[a];
    __syncthreads();
    for (int c = tid; c < 512; c += 256)
        g_pssq[(size_t)blockIdx.x*512 + c] = sred[c] + sred[512 + c];
}

// ---------------- final: norm-relu + max over 128 centroids ------------------------
__global__ void k_final(float* __restrict__ out) {
    int idx = blockIdx.x * blockDim.x + threadIdx.x;
    if (idx >= B_*512) return;
    int oc = idx & 511, b = idx >> 9;
    float a = g_scale[2048 + oc], bb = g_bias[2048 + oc];
    const float* base = g_y3 + (size_t)b*S2_*512 + oc;
    float m = 0.f;
#pragma unroll 8
    for (int p = 0; p < S2_; p++) {
        float v = fmaxf(fmaf(base[p*512], a, bb), 0.f);
        m = fmaxf(m, v);
    }
    out[idx] = m;
}

// ---------------- host ----------------
extern "C" void kernel_launch(void* const* d_in, const int* in_sizes, int n_in,
                              void* d_out, int out_size) {
    const float* pc  = (const float*)d_in[0];
    const float* w1a = (const float*)d_in[1];
    const float* g1a = (const float*)d_in[2];
    const float* b1a = (const float*)d_in[3];
    const float* w1b = (const float*)d_in[4];
    const float* g1b = (const float*)d_in[5];
    const float* b1b = (const float*)d_in[6];
    const float* w2a = (const float*)d_in[7];
    const float* g2a = (const float*)d_in[8];
    const float* b2a = (const float*)d_in[9];
    const float* w2b = (const float*)d_in[10];
    const float* g2b = (const float*)d_in[11];
    const float* b2b = (const float*)d_in[12];
    const float* w3  = (const float*)d_in[13];
    const float* g3  = (const float*)d_in[14];
    const float* b3  = (const float*)d_in[15];
    float* out = (float*)d_out;

    float *xyz, *xyz1, *xyz2, *scale, *bias;
    int *fi1, *fi2, *ni1, *ni2;
    double *psum, *pssq;
    cudaGetSymbolAddress((void**)&xyz,   g_xyz);
    cudaGetSymbolAddress((void**)&xyz1,  g_xyz1);
    cudaGetSymbolAddress((void**)&xyz2,  g_xyz2);
    cudaGetSymbolAddress((void**)&fi1,   g_fi1);
    cudaGetSymbolAddress((void**)&fi2,   g_fi2);
    cudaGetSymbolAddress((void**)&ni1,   g_ni1);
    cudaGetSymbolAddress((void**)&ni2,   g_ni2);
    cudaGetSymbolAddress((void**)&psum,  g_psum);
    cudaGetSymbolAddress((void**)&pssq,  g_pssq);
    cudaGetSymbolAddress((void**)&scale, g_scale);
    cudaGetSymbolAddress((void**)&bias,  g_bias);

    k_prep<<<1672, 256>>>(pc, w1b, w2a, w2b, w3);

    // stage 1
    k_fps<8><<<32, 256>>>(xyz, 2048, 512, fi1, xyz1);
    k_ballquery<<<2048, 256>>>(xyz, xyz1, ni1, 2048, 512, 48,
                               (float)(0.23*0.23), 32*512);
    k_stats6<<<768, 256>>>();
    k_quad6<<<1, 256>>>(w1a, g1a, b1a);
    k_fused1b<<<16384, 256>>>(w1a);
    k_finalize<<<128, 256>>>(psum, pssq, 16384, 128, 786432.0,
                             g1b, b1b, scale + 512, bias + 512);

    // stage 2
    k_fps<2><<<32, 256>>>(xyz1, 512, 128, fi2, xyz2);
    k_ballquery<<<512, 256>>>(xyz1, xyz2, ni2, 512, 128, 64,
                              (float)(0.32*0.32), 32*128);
    k_layer2a_t<<<8192, 256>>>();
    k_finalize<<<128, 256>>>(psum, pssq, 8192, 128, 262144.0,
                             g2a, b2a, scale + 1024, bias + 1024);
    k_fused2b<<<8192, 256>>>();
    k_finalize<<<512, 256>>>(psum, pssq, 4096, 512, 262144.0,
                             g2b, b2b, scale + 1536, bias + 1536);

    // stage 3
    k_layer3_t<<<256, 256>>>();
    k_finalize<<<512, 256>>>(psum, pssq, 256, 512, 4096.0,
                             g3, b3, scale + 2048, bias + 2048);
    k_final<<<64, 256>>>(out);
}